// round 9
// baseline (speedup 1.0000x reference)
#include <cuda_runtime.h>
#include <cstdint>

#define NN   100000
#define EE   1600000
#define FIN  128
#define HH   128
#define OUTC 64

// ---------------- scratch (no allocation allowed) ----------------
__device__ __align__(16) int   g_cnt[NN];
__device__ __align__(16) int   g_rowptr[NN + 1];
__device__ __align__(16) int   g_cursor[NN];
__device__ __align__(16) int   g_bsum[256];
__device__ __align__(16) float g_dinv[NN];
__device__ __align__(16) int   g_csr_src[EE];
__device__ __align__(16) float g_csr_dinv[EE];          // dinv[src] per CSR slot (coalesced in agg)
__device__ __align__(16) float g_t[(size_t)NN * HH];    // GEMM output (UNscaled)
__device__ __align__(16) float g_h[(size_t)NN * HH];    // layer activation

// ================= CSR construction =================
__global__ void k_zero(int n) {
    int i = blockIdx.x * blockDim.x + threadIdx.x;
    if (i < n) g_cnt[i] = 0;
}
__global__ void k_count(const int* __restrict__ dst, int e) {
    int i = blockIdx.x * blockDim.x + threadIdx.x;
    if (i < e) atomicAdd(&g_cnt[dst[i]], 1);
}
__global__ void k_scan1(int n) {
    __shared__ int sh[1024];
    int tid = threadIdx.x;
    int i = blockIdx.x * 1024 + tid;
    int v = (i < n) ? g_cnt[i] : 0;
    sh[tid] = v;
    __syncthreads();
#pragma unroll
    for (int off = 1; off < 1024; off <<= 1) {
        int t = (tid >= off) ? sh[tid - off] : 0;
        __syncthreads();
        sh[tid] += t;
        __syncthreads();
    }
    if (i < n) {
        g_rowptr[i] = sh[tid] - v;                 // exclusive, local
        g_dinv[i]   = rsqrtf(1.0f + (float)v);     // +1 self-loop
    }
    if (tid == 1023) g_bsum[blockIdx.x] = sh[1023];
}
__global__ void k_scan2(int nb, int n) {
    __shared__ int sh[128];
    int tid = threadIdx.x;
    int v = (tid < nb) ? g_bsum[tid] : 0;
    sh[tid] = v;
    __syncthreads();
#pragma unroll
    for (int off = 1; off < 128; off <<= 1) {
        int t = (tid >= off) ? sh[tid - off] : 0;
        __syncthreads();
        sh[tid] += t;
        __syncthreads();
    }
    if (tid < nb) g_bsum[tid] = sh[tid] - v;
    if (tid == 127) g_rowptr[n] = sh[127];
}
__global__ void k_scan3(int n) {
    int i = blockIdx.x * blockDim.x + threadIdx.x;
    if (i >= n) return;
    int v = g_rowptr[i] + g_bsum[i >> 10];
    g_rowptr[i] = v;
    g_cursor[i] = v;
}
__global__ void k_fill(const int* __restrict__ src, const int* __restrict__ dst, int e) {
    int i = blockIdx.x * blockDim.x + threadIdx.x;
    if (i >= e) return;
    int d = dst[i];
    int s = src[i];
    int pos = atomicAdd(&g_cursor[d], 1);
    g_csr_src[pos]  = s;
    g_csr_dinv[pos] = g_dinv[s];
}

// ================= bf16-split helpers =================
// v = hi + lo with hi,lo bf16; dropped lo*lo term ~2^-16 relative.
__device__ __forceinline__ void pack_split(float2 v, uint32_t& hi, uint32_t& lo) {
    asm("cvt.rn.bf16x2.f32 %0, %1, %2;" : "=r"(hi) : "f"(v.y), "f"(v.x));  // lo half = v.x
    float h0 = __uint_as_float(hi << 16);
    float h1 = __uint_as_float(hi & 0xFFFF0000u);
    float l0 = v.x - h0;
    float l1 = v.y - h1;
    asm("cvt.rn.bf16x2.f32 %0, %1, %2;" : "=r"(lo) : "f"(l1), "f"(l0));
}
__device__ __forceinline__ void mma_bf16(float c[4], const uint32_t a[4], const uint32_t b[2]) {
    asm volatile(
        "mma.sync.aligned.m16n8k16.row.col.f32.bf16.bf16.f32 "
        "{%0,%1,%2,%3}, {%4,%5,%6,%7}, {%8,%9}, {%0,%1,%2,%3};"
        : "+f"(c[0]), "+f"(c[1]), "+f"(c[2]), "+f"(c[3])
        : "r"(a[0]), "r"(a[1]), "r"(a[2]), "r"(a[3]), "r"(b[0]), "r"(b[1]));
}

// ================= GEMM: g_t[M,DOUT] = A[M,128] @ W[128,DOUT] (unscaled) =================
// 256 threads (8 warps, 2m x 4n), CTA tile 64 x DOUT. bf16-split, 3 MMAs per k16.
template<int DOUT>
__global__ __launch_bounds__(256, 2)
void k_gemm(const float* __restrict__ Ax, const float* __restrict__ W,
            int M, int from_h) {
    constexpr int DIN = 128;
    constexpr int AST = DIN + 8;      // 136: LDS.64 A-frag conflict-free (8g+2t)
    constexpr int WST = DOUT + 4;     // LDS.32 B-frag conflict-free (8t'+g)
    constexpr int NT  = DOUT / 32;    // n8-tiles per warp (4 or 2)

    extern __shared__ float sm[];
    float* As = sm;                   // [64][AST]
    float* Ws = sm + 64 * AST;        // [128][WST]  row=k, col=n

    const float* A = from_h ? g_h : Ax;
    int tid  = threadIdx.x;
    int row0 = blockIdx.x * 64;

    for (int i = tid; i < DIN * (DOUT / 4); i += 256) {
        int r  = i / (DOUT / 4);
        int c4 = i % (DOUT / 4);
        *(float4*)(Ws + r * WST + c4 * 4) = ((const float4*)W)[i];
    }
    for (int i = tid; i < 64 * 32; i += 256) {
        int r  = i >> 5;
        int c4 = i & 31;
        int gr = row0 + r;
        float4 v = make_float4(0.f, 0.f, 0.f, 0.f);
        if (gr < M) v = ((const float4*)A)[(size_t)gr * 32 + c4];
        *(float4*)(As + r * AST + c4 * 4) = v;
    }
    __syncthreads();

    int warp = tid >> 5, lane = tid & 31;
    int wm = warp & 1;                 // 0..1
    int wn = warp >> 1;                // 0..3
    int g  = lane >> 2;                // 0..7
    int t  = lane & 3;                 // 0..3
    int mbase = wm * 32;
    int nbase = wn * (DOUT / 4);

    float acc[2][NT][4];
#pragma unroll
    for (int i = 0; i < 2; i++)
#pragma unroll
        for (int j = 0; j < NT; j++)
#pragma unroll
            for (int q = 0; q < 4; q++) acc[i][j][q] = 0.f;

#pragma unroll 2
    for (int kk = 0; kk < DIN; kk += 16) {
        uint32_t ahi[2][4], alo[2][4];
#pragma unroll
        for (int i = 0; i < 2; i++) {
            const float* p = As + (mbase + i * 16 + g) * AST + kk + 2 * t;
            float2 v00 = *(const float2*)(p);                 // a0: row g,   k 2t..2t+1
            float2 v10 = *(const float2*)(p + 8 * AST);       // a1: row g+8
            float2 v01 = *(const float2*)(p + 8);             // a2: row g,   k+8
            float2 v11 = *(const float2*)(p + 8 * AST + 8);   // a3: row g+8, k+8
            pack_split(v00, ahi[i][0], alo[i][0]);
            pack_split(v10, ahi[i][1], alo[i][1]);
            pack_split(v01, ahi[i][2], alo[i][2]);
            pack_split(v11, ahi[i][3], alo[i][3]);
        }
        uint32_t bhi[NT][2], blo[NT][2];
#pragma unroll
        for (int j = 0; j < NT; j++) {
            const float* q = Ws + (kk + 2 * t) * WST + nbase + j * 8 + g;
            float2 u0 = make_float2(q[0], q[WST]);            // b0: k 2t, 2t+1
            float2 u1 = make_float2(q[8 * WST], q[9 * WST]);  // b1: k 2t+8, 2t+9
            pack_split(u0, bhi[j][0], blo[j][0]);
            pack_split(u1, bhi[j][1], blo[j][1]);
        }
#pragma unroll
        for (int i = 0; i < 2; i++)
#pragma unroll
            for (int j = 0; j < NT; j++) {
                mma_bf16(acc[i][j], ahi[i], bhi[j]);
                mma_bf16(acc[i][j], ahi[i], blo[j]);
                mma_bf16(acc[i][j], alo[i], bhi[j]);
            }
    }

    // epilogue: plain store (no scaling — dinv folded into agg)
#pragma unroll
    for (int i = 0; i < 2; i++) {
        int r_lo = row0 + mbase + i * 16 + g;
        int r_hi = r_lo + 8;
#pragma unroll
        for (int j = 0; j < NT; j++) {
            int col = nbase + j * 8 + 2 * t;
            if (r_lo < M)
                *(float2*)&g_t[(size_t)r_lo * DOUT + col] =
                    make_float2(acc[i][j][0], acc[i][j][1]);
            if (r_hi < M)
                *(float2*)&g_t[(size_t)r_hi * DOUT + col] =
                    make_float2(acc[i][j][2], acc[i][j][3]);
        }
    }
}

// ================= Aggregation (warp per node), fused epilogue =================
// acc = dinv_i*t_i + sum_s dinv_s*t_s ; res = dinv_i*acc + bias
template<int DOUT, int MODE>
__global__ void k_agg(const float* __restrict__ bias, float* __restrict__ out, int n) {
    int w    = (blockIdx.x * blockDim.x + threadIdx.x) >> 5;
    int lane = threadIdx.x & 31;
    if (w >= n) return;
    constexpr int VF = DOUT / 32;

    float di = g_dinv[w];
    float acc[VF];
    {   // self term: dinv_i * t_i
        const float* p = g_t + (size_t)w * DOUT + lane * VF;
        if (VF == 4) { float4 v = *(const float4*)p;
            acc[0]=di*v.x; acc[1]=di*v.y; acc[2]=di*v.z; acc[3]=di*v.w; }
        else         { float2 v = *(const float2*)p;
            acc[0]=di*v.x; acc[1]=di*v.y; }
    }

    int beg = g_rowptr[w], end = g_rowptr[w + 1];
    for (int jb = beg; jb < end; jb += 32) {
        int myj = jb + lane;
        int   ms = (myj < end) ? g_csr_src[myj]  : 0;
        float mw = (myj < end) ? g_csr_dinv[myj] : 0.f;
        int cnt = min(32, end - jb);
        int k = 0;
        for (; k + 4 <= cnt; k += 4) {
            int s0 = __shfl_sync(0xffffffffu, ms, k);
            int s1 = __shfl_sync(0xffffffffu, ms, k + 1);
            int s2 = __shfl_sync(0xffffffffu, ms, k + 2);
            int s3 = __shfl_sync(0xffffffffu, ms, k + 3);
            float d0 = __shfl_sync(0xffffffffu, mw, k);
            float d1 = __shfl_sync(0xffffffffu, mw, k + 1);
            float d2 = __shfl_sync(0xffffffffu, mw, k + 2);
            float d3 = __shfl_sync(0xffffffffu, mw, k + 3);
            if (VF == 4) {
                float4 v0 = *(const float4*)(g_t + (size_t)s0 * DOUT + lane * 4);
                float4 v1 = *(const float4*)(g_t + (size_t)s1 * DOUT + lane * 4);
                float4 v2 = *(const float4*)(g_t + (size_t)s2 * DOUT + lane * 4);
                float4 v3 = *(const float4*)(g_t + (size_t)s3 * DOUT + lane * 4);
                acc[0] += (fmaf(d0,v0.x,d1*v1.x)) + (fmaf(d2,v2.x,d3*v3.x));
                acc[1] += (fmaf(d0,v0.y,d1*v1.y)) + (fmaf(d2,v2.y,d3*v3.y));
                acc[2] += (fmaf(d0,v0.z,d1*v1.z)) + (fmaf(d2,v2.z,d3*v3.z));
                acc[3] += (fmaf(d0,v0.w,d1*v1.w)) + (fmaf(d2,v2.w,d3*v3.w));
            } else {
                float2 v0 = *(const float2*)(g_t + (size_t)s0 * DOUT + lane * 2);
                float2 v1 = *(const float2*)(g_t + (size_t)s1 * DOUT + lane * 2);
                float2 v2 = *(const float2*)(g_t + (size_t)s2 * DOUT + lane * 2);
                float2 v3 = *(const float2*)(g_t + (size_t)s3 * DOUT + lane * 2);
                acc[0] += (fmaf(d0,v0.x,d1*v1.x)) + (fmaf(d2,v2.x,d3*v3.x));
                acc[1] += (fmaf(d0,v0.y,d1*v1.y)) + (fmaf(d2,v2.y,d3*v3.y));
            }
        }
        for (; k < cnt; k++) {
            int   s = __shfl_sync(0xffffffffu, ms, k);
            float d = __shfl_sync(0xffffffffu, mw, k);
            if (VF == 4) {
                float4 v = *(const float4*)(g_t + (size_t)s * DOUT + lane * 4);
                acc[0] = fmaf(d, v.x, acc[0]); acc[1] = fmaf(d, v.y, acc[1]);
                acc[2] = fmaf(d, v.z, acc[2]); acc[3] = fmaf(d, v.w, acc[3]);
            } else {
                float2 v = *(const float2*)(g_t + (size_t)s * DOUT + lane * 2);
                acc[0] = fmaf(d, v.x, acc[0]); acc[1] = fmaf(d, v.y, acc[1]);
            }
        }
    }

    if (MODE == 0) {
        float4 bb = ((const float4*)bias)[lane];
        float4 r;
        r.x = fmaxf(fmaf(di, acc[0], bb.x), 0.f);
        r.y = fmaxf(fmaf(di, acc[1], bb.y), 0.f);
        r.z = fmaxf(fmaf(di, acc[2], bb.z), 0.f);
        r.w = fmaxf(fmaf(di, acc[3], bb.w), 0.f);
        *(float4*)(g_h + (size_t)w * DOUT + lane * 4) = r;
    } else {
        float2 bb = ((const float2*)bias)[lane];
        float vx = fmaf(di, acc[0], bb.x);
        float vy = fmaf(di, acc[1], bb.y);
        float m = fmaxf(vx, vy);
#pragma unroll
        for (int o = 16; o; o >>= 1) m = fmaxf(m, __shfl_xor_sync(0xffffffffu, m, o));
        float sum = expf(vx - m) + expf(vy - m);
#pragma unroll
        for (int o = 16; o; o >>= 1) sum += __shfl_xor_sync(0xffffffffu, sum, o);
        float lse = m + logf(sum);
        *(float2*)(out + (size_t)w * 64 + lane * 2) = make_float2(vx - lse, vy - lse);
    }
}

// ================= launch =================
extern "C" void kernel_launch(void* const* d_in, const int* in_sizes, int n_in,
                              void* d_out, int out_size) {
    const float* x   = (const float*)d_in[0];
    const int*   ei  = (const int*)d_in[1];     // int32 (JAX x64 disabled)
    const float* W1  = (const float*)d_in[2];
    const float* b1  = (const float*)d_in[3];
    const float* W2  = (const float*)d_in[4];
    const float* b2  = (const float*)d_in[5];
    const float* W3  = (const float*)d_in[6];
    const float* b3  = (const float*)d_in[7];
    float* out = (float*)d_out;

    int n = in_sizes[0] / FIN;
    int e = in_sizes[1] / 2;
    const int* srcp = ei;
    const int* dstp = ei + e;

    // one-time side stream + events (created on the non-captured correctness call)
    static cudaStream_t s2 = [] { cudaStream_t s; cudaStreamCreate(&s); return s; }();
    static cudaEvent_t ev0 = [] { cudaEvent_t ev; cudaEventCreateWithFlags(&ev, cudaEventDisableTiming); return ev; }();
    static cudaEvent_t ev2 = [] { cudaEvent_t ev; cudaEventCreateWithFlags(&ev, cudaEventDisableTiming); return ev; }();

    const int smem128 = (64 * (FIN + 8) + 128 * (HH   + 4)) * sizeof(float); // ~100 KB -> 2 CTA/SM
    const int smem64  = (64 * (FIN + 8) + 128 * (OUTC + 4)) * sizeof(float); // ~68 KB
    cudaFuncSetAttribute(k_gemm<HH>,   cudaFuncAttributeMaxDynamicSharedMemorySize, smem128);
    cudaFuncSetAttribute(k_gemm<OUTC>, cudaFuncAttributeMaxDynamicSharedMemorySize, smem64);

    int nb_scan = (n + 1023) >> 10;
    int gemm_blocks = (n + 63) / 64;
    int agg_blocks  = (int)(((long long)n * 32 + 255) / 256);

    // fork: CSR chain on side stream, gemm1 (independent of CSR) on main stream
    cudaEventRecord(ev0, 0);
    cudaStreamWaitEvent(s2, ev0, 0);

    k_zero <<<(n + 255) / 256, 256, 0, s2>>>(n);               // 1
    k_count<<<(e + 255) / 256, 256, 0, s2>>>(dstp, e);         // 2
    k_scan1<<<nb_scan, 1024, 0, s2>>>(n);                      // 3 (also dinv)
    k_gemm<HH><<<gemm_blocks, 256, smem128>>>(x, W1, n, 0);    // 4 <-- profiled (main stream)
    k_scan2<<<1, 128, 0, s2>>>(nb_scan, n);                    // 5
    k_scan3<<<(n + 255) / 256, 256, 0, s2>>>(n);               // 6
    k_fill <<<(e + 255) / 256, 256, 0, s2>>>(srcp, dstp, e);   // 7

    // join: aggregation needs both CSR and gemm1
    cudaEventRecord(ev2, s2);
    cudaStreamWaitEvent(0, ev2, 0);

    k_agg<HH, 0><<<agg_blocks, 256>>>(b1, nullptr, n);
    k_gemm<HH><<<gemm_blocks, 256, smem128>>>(x, W2, n, 1);
    k_agg<HH, 0><<<agg_blocks, 256>>>(b2, nullptr, n);
    k_gemm<OUTC><<<gemm_blocks, 256, smem64>>>(x, W3, n, 1);
    k_agg<OUTC, 1><<<agg_blocks, 256>>>(b3, out, n);
}